// round 1
// baseline (speedup 1.0000x reference)
#include <cuda_runtime.h>
#include <cuda_bf16.h>

#define K_F 16
#define T_TYPES 4
#define OUT_W (K_F * T_TYPES)

__global__ void zero_out_kernel(float4* __restrict__ out, int n4) {
    int i = blockIdx.x * blockDim.x + threadIdx.x;
    if (i < n4) out[i] = make_float4(0.f, 0.f, 0.f, 0.f);
}

__global__ void __launch_bounds__(256) edge_kernel(
    const float* __restrict__ feat,      // (V,1) atom-type ids as floats
    const float* __restrict__ dist,      // (E,1)
    const int*   __restrict__ src,       // (E,)
    const int*   __restrict__ dst,       // (E,)
    const float* __restrict__ cutoffs,   // (K,)
    const float* __restrict__ means,     // (K,)
    const float* __restrict__ scaling,   // (K,)
    const float* __restrict__ ftu,       // (T,)
    float*       __restrict__ out,       // (V, T*K)
    int E)
{
    __shared__ float s_cut[K_F], s_mean[K_F], s_scal[K_F], s_ftu[T_TYPES];
    if (threadIdx.x < K_F) {
        s_cut[threadIdx.x]  = cutoffs[threadIdx.x];
        s_mean[threadIdx.x] = means[threadIdx.x];
        s_scal[threadIdx.x] = scaling[threadIdx.x];
    }
    if (threadIdx.x < T_TYPES) s_ftu[threadIdx.x] = ftu[threadIdx.x];
    __syncthreads();

    int e = blockIdx.x * blockDim.x + threadIdx.x;
    if (e >= E) return;

    float d  = dist[e];
    int   s  = src[e];
    int   dd = dst[e];
    float fv = __ldg(&feat[s]);

    int type = -1;
    #pragma unroll
    for (int j = 0; j < T_TYPES; j++)
        if (fv == s_ftu[j]) type = j;
    if (type < 0) return;   // no one-hot match -> zero contribution

    float he[K_F];
    #pragma unroll
    for (int k = 0; k < K_F; k++) {
        float dm  = d - s_mean[k];
        float rbf = __expf(-s_scal[k] * dm * dm);
        float c   = s_cut[k];
        float cv  = 0.5f * (__cosf(3.14159265358979323846f * d / c) + 1.0f);
        he[k] = (d <= c) ? rbf * cv : 0.0f;
    }

    // out[dd, type*K .. type*K+15]: contiguous, 16B-aligned (type*16 floats)
    float* p = out + (size_t)dd * OUT_W + type * K_F;
    #pragma unroll
    for (int k = 0; k < K_F; k += 4) {
        asm volatile(
            "red.global.add.v4.f32 [%0], {%1, %2, %3, %4};"
            :: "l"(p + k), "f"(he[k]), "f"(he[k + 1]), "f"(he[k + 2]), "f"(he[k + 3])
            : "memory");
    }
}

extern "C" void kernel_launch(void* const* d_in, const int* in_sizes, int n_in,
                              void* d_out, int out_size)
{
    const float* feat    = (const float*)d_in[0];
    const float* dist    = (const float*)d_in[1];
    const int*   src     = (const int*)  d_in[2];
    const int*   dst     = (const int*)  d_in[3];
    const float* cutoffs = (const float*)d_in[4];
    const float* means   = (const float*)d_in[5];
    const float* scaling = (const float*)d_in[6];
    const float* ftu     = (const float*)d_in[7];
    float* out = (float*)d_out;

    int E = in_sizes[2];           // src element count

    int n4 = out_size / 4;
    zero_out_kernel<<<(n4 + 255) / 256, 256>>>((float4*)out, n4);

    edge_kernel<<<(E + 255) / 256, 256>>>(
        feat, dist, src, dst, cutoffs, means, scaling, ftu, out, E);
}

// round 2
// speedup vs baseline: 1.0276x; 1.0276x over previous
#include <cuda_runtime.h>
#include <cuda_bf16.h>

#define K_F 16
#define T_TYPES 4
#define OUT_W (K_F * T_TYPES)
#define PI_F 3.14159265358979323846f

__global__ void zero_out_kernel(float4* __restrict__ out, int n4) {
    int i = blockIdx.x * blockDim.x + threadIdx.x;
    if (i < n4) out[i] = make_float4(0.f, 0.f, 0.f, 0.f);
}

// 4 lanes cooperate on one edge: lane quad q handles edge, lane%4 selects the
// 4-wide k-chunk. The quad's four red.v4 ops cover one contiguous, 64B-aligned
// region -> coalesced into 2 sectors on a single 128B line (vs 4 separate
// random 16B requests in the thread-per-edge version).
__global__ void __launch_bounds__(256) edge_kernel(
    const float* __restrict__ feat,      // (V,1) atom-type ids as floats
    const float* __restrict__ dist,      // (E,1)
    const int*   __restrict__ src,       // (E,)
    const int*   __restrict__ dst,       // (E,)
    const float* __restrict__ cutoffs,   // (K,)
    const float* __restrict__ means,     // (K,)
    const float* __restrict__ scaling,   // (K,)
    const float* __restrict__ ftu,       // (T,)
    float*       __restrict__ out,       // (V, T*K)
    int E)
{
    __shared__ float s_cut[K_F], s_mean[K_F], s_scal[K_F], s_ftu[T_TYPES];
    __shared__ int s_uni;
    if (threadIdx.x < K_F) {
        s_cut[threadIdx.x]  = cutoffs[threadIdx.x];
        s_mean[threadIdx.x] = means[threadIdx.x];
        s_scal[threadIdx.x] = scaling[threadIdx.x];
    }
    if (threadIdx.x < T_TYPES) s_ftu[threadIdx.x] = ftu[threadIdx.x];
    if (threadIdx.x == 0) {
        int u = 1;
        #pragma unroll
        for (int k = 1; k < K_F; k++) u &= (cutoffs[k] == cutoffs[0]);
        s_uni = u;
    }
    __syncthreads();

    int gid = blockIdx.x * 256 + threadIdx.x;
    int e = gid >> 2;          // edge index
    int c = gid & 3;           // k-chunk (0..3)
    if (e >= E) return;

    // Same-address lanes within the quad coalesce to a single request.
    float d  = dist[e];
    int   s  = src[e];
    int   dd = dst[e];
    float fv = __ldg(&feat[s]);

    int type = -1;
    #pragma unroll
    for (int j = 0; j < T_TYPES; j++)
        if (fv == s_ftu[j]) type = j;
    if (type < 0) return;      // no one-hot match -> zero contribution

    int k0 = c * 4;
    float v0, v1, v2, v3;

    if (s_uni) {
        // All cutoffs identical (common case): one cosine per edge-lane.
        float cu = s_cut[0];
        float cv = (d <= cu) ? 0.5f * (__cosf(PI_F * d / cu) + 1.0f) : 0.0f;
        float dm0 = d - s_mean[k0 + 0];
        float dm1 = d - s_mean[k0 + 1];
        float dm2 = d - s_mean[k0 + 2];
        float dm3 = d - s_mean[k0 + 3];
        v0 = cv * __expf(-s_scal[k0 + 0] * dm0 * dm0);
        v1 = cv * __expf(-s_scal[k0 + 1] * dm1 * dm1);
        v2 = cv * __expf(-s_scal[k0 + 2] * dm2 * dm2);
        v3 = cv * __expf(-s_scal[k0 + 3] * dm3 * dm3);
    } else {
        float v[4];
        #pragma unroll
        for (int i = 0; i < 4; i++) {
            int k = k0 + i;
            float cu  = s_cut[k];
            float cv  = (d <= cu) ? 0.5f * (__cosf(PI_F * d / cu) + 1.0f) : 0.0f;
            float dm  = d - s_mean[k];
            v[i] = cv * __expf(-s_scal[k] * dm * dm);
        }
        v0 = v[0]; v1 = v[1]; v2 = v[2]; v3 = v[3];
    }

    // out[dd, type*16 + k0 .. +3]: quad covers one 64B-aligned 64B region.
    float* p = out + (size_t)dd * OUT_W + type * K_F + k0;
    asm volatile(
        "red.global.add.v4.f32 [%0], {%1, %2, %3, %4};"
        :: "l"(p), "f"(v0), "f"(v1), "f"(v2), "f"(v3)
        : "memory");
}

extern "C" void kernel_launch(void* const* d_in, const int* in_sizes, int n_in,
                              void* d_out, int out_size)
{
    const float* feat    = (const float*)d_in[0];
    const float* dist    = (const float*)d_in[1];
    const int*   src     = (const int*)  d_in[2];
    const int*   dst     = (const int*)  d_in[3];
    const float* cutoffs = (const float*)d_in[4];
    const float* means   = (const float*)d_in[5];
    const float* scaling = (const float*)d_in[6];
    const float* ftu     = (const float*)d_in[7];
    float* out = (float*)d_out;

    int E = in_sizes[2];           // src element count

    int n4 = out_size / 4;
    zero_out_kernel<<<(n4 + 255) / 256, 256>>>((float4*)out, n4);

    long long work = 4LL * E;
    int blocks = (int)((work + 255) / 256);
    edge_kernel<<<blocks, 256>>>(
        feat, dist, src, dst, cutoffs, means, scaling, ftu, out, E);
}

// round 4
// speedup vs baseline: 1.2242x; 1.1913x over previous
#include <cuda_runtime.h>
#include <cuda_bf16.h>

#define K_F 16
#define T_TYPES 4
#define OUT_W (K_F * T_TYPES)
#define PI_F 3.14159265358979323846f
#define BLK 256

__global__ void zero_out_kernel(float4* __restrict__ out, int n4) {
    int i = blockIdx.x * blockDim.x + threadIdx.x;
    if (i < n4) out[i] = make_float4(0.f, 0.f, 0.f, 0.f);
}

// One thread computes one edge's 16 values; an smem transpose then lets each
// lane-quad issue 4 contiguous red.v4 covering a single 64B-aligned region
// (R2's coalesced RED pattern) without R2's 4x instruction duplication.
__global__ void __launch_bounds__(BLK) edge_kernel(
    const float* __restrict__ feat,      // (V,1)
    const float* __restrict__ dist,      // (E,1)
    const int*   __restrict__ src,       // (E,)
    const int*   __restrict__ dst,       // (E,)
    const float* __restrict__ cutoffs,   // (K,)
    const float* __restrict__ means,     // (K,)
    const float* __restrict__ scaling,   // (K,)
    const float* __restrict__ ftu,       // (T,)
    float*       __restrict__ out,       // (V, T*K)
    int E)
{
    __shared__ float s_mean[K_F], s_nscal[K_F], s_cut[K_F], s_ftu[T_TYPES];
    __shared__ int s_unicos;
    // 5 float4-units per edge (80B): stride 5 is conflict-free for both the
    // write (tid*5+c) and the transposed read ((q*4+i)*5+c) phases.
    __shared__ float4 s_val[BLK * 5];
    __shared__ unsigned long long s_ptr[BLK];

    int tid = threadIdx.x;
    if (tid < K_F) {
        s_mean[tid]  = means[tid];
        s_nscal[tid] = -scaling[tid];
        s_cut[tid]   = cutoffs[tid];
    }
    if (tid < T_TYPES) s_ftu[tid] = ftu[tid];
    if (tid == 0) {
        int u = 1;
        #pragma unroll
        for (int k = 1; k < K_F; k++) u &= (cutoffs[k] == cutoffs[0]);
        s_unicos = u;
    }
    __syncthreads();

    int e = blockIdx.x * BLK + tid;
    float v[K_F];
    unsigned long long p = 0;

    if (e < E) {
        float d  = dist[e];
        int   s  = src[e];
        int   dd = dst[e];
        float fv = __ldg(&feat[s]);

        int type = -1;
        #pragma unroll
        for (int j = 0; j < T_TYPES; j++)
            if (fv == s_ftu[j]) type = j;

        if (type >= 0) {
            p = (unsigned long long)(out + (size_t)dd * OUT_W + type * K_F);
            if (s_unicos) {
                float cu = s_cut[0];
                float cv = (d <= cu) ? 0.5f * (__cosf(PI_F * d / cu) + 1.0f) : 0.0f;
                #pragma unroll
                for (int k = 0; k < K_F; k++) {
                    float dm = d - s_mean[k];
                    v[k] = cv * __expf(s_nscal[k] * dm * dm);
                }
            } else {
                #pragma unroll
                for (int k = 0; k < K_F; k++) {
                    float cu = s_cut[k];
                    float cv = (d <= cu) ? 0.5f * (__cosf(PI_F * d / cu) + 1.0f) : 0.0f;
                    float dm = d - s_mean[k];
                    v[k] = cv * __expf(s_nscal[k] * dm * dm);
                }
            }
        }
    }
    if (p == 0) {
        #pragma unroll
        for (int k = 0; k < K_F; k++) v[k] = 0.0f;
    }

    // Stage values + target pointer in smem.
    float4* slot = &s_val[tid * 5];
    slot[0] = make_float4(v[0],  v[1],  v[2],  v[3]);
    slot[1] = make_float4(v[4],  v[5],  v[6],  v[7]);
    slot[2] = make_float4(v[8],  v[9],  v[10], v[11]);
    slot[3] = make_float4(v[12], v[13], v[14], v[15]);
    s_ptr[tid] = p;
    __syncthreads();

    // Transposed RED: quad q, step i -> edge q*4+i; lane chunk c = tid&3.
    int q = tid >> 2;
    int c = tid & 3;
    #pragma unroll
    for (int i = 0; i < 4; i++) {
        int el = q * 4 + i;
        unsigned long long tp = s_ptr[el];
        if (tp) {
            float4 val = s_val[el * 5 + c];
            float* addr = (float*)tp + c * 4;
            asm volatile(
                "red.global.add.v4.f32 [%0], {%1, %2, %3, %4};"
                :: "l"(addr), "f"(val.x), "f"(val.y), "f"(val.z), "f"(val.w)
                : "memory");
        }
    }
}

extern "C" void kernel_launch(void* const* d_in, const int* in_sizes, int n_in,
                              void* d_out, int out_size)
{
    const float* feat    = (const float*)d_in[0];
    const float* dist    = (const float*)d_in[1];
    const int*   src     = (const int*)  d_in[2];
    const int*   dst     = (const int*)  d_in[3];
    const float* cutoffs = (const float*)d_in[4];
    const float* means   = (const float*)d_in[5];
    const float* scaling = (const float*)d_in[6];
    const float* ftu     = (const float*)d_in[7];
    float* out = (float*)d_out;

    int E = in_sizes[2];

    int n4 = out_size / 4;
    zero_out_kernel<<<(n4 + 255) / 256, 256>>>((float4*)out, n4);

    edge_kernel<<<(E + BLK - 1) / BLK, BLK>>>(
        feat, dist, src, dst, cutoffs, means, scaling, ftu, out, E);
}